// round 16
// baseline (speedup 1.0000x reference)
#include <cuda_runtime.h>
#include <cuda_bf16.h>
#include <float.h>

// Chamfer distance, B=4, N=M=4096, D=3 — tensor-core mma.sync, v5.
// = R13 (best mainloop) + __launch_bounds__(128,7): regs<=65 so all 1024
// CTAs are resident in ONE wave (7/SM), removing the second-wave tail that
// dominated R13's stall time.
// One m16n8k16 bf16 MMA yields 128 FINAL squared distances via exact 2-term
// bf16 split (k map:  A: qhi.xyz qlo.xyz qhi.xyz qlo.xyz np_hi np_lo 1 1
//                     B: ghi.xyz ghi.xyz glo.xyz glo.xyz 1 1 w_hi w_lo
//  dot = (qhi+qlo).(ghi+glo) + np + w = |p-g|^2, fp32 accum).
// 32 rows/warp (2 A frags), ldmatrix.x4 B frags (1 LDSM -> 4 HMMAs),
// double-buffered B stages (encode overlapped with MMA). Row mins in regs;
// both directions as role-swapped passes. Cross-CTA combine: atomicMax on
// key 0x7F7FFFFF - bits(d>=0) (zero-init identity, no init kernel); last
// CTA decodes/sums fixed-order, resets slots. Deterministic.

#define BATCH 4
#define NPTS  4096
#define TPB   128
#define ROWS_PER_CTA 128                     // 32 rows per warp
#define ROWCHUNKS (NPTS / ROWS_PER_CTA)      // 32
#define COLSPLIT 4
#define COLS_PER_CTA (NPTS / COLSPLIT)       // 1024
#define STAGE_COLS 256
#define NSTAGES (COLS_PER_CTA / STAGE_COLS)  // 4
#define UNITS_PER_STAGE (STAGE_COLS / 16)    // 16
#define ROW_STRIDE 24                        // bf16 elems per smem row (48B)
#define NSLOTS (2 * BATCH * NPTS)            // 32768
#define NCTAS (ROWCHUNKS * COLSPLIT * BATCH * 2)  // 1024

__device__ unsigned int g_maxkey[NSLOTS];    // 0 == key(FLT_MAX): identity
__device__ unsigned int g_count = 0;

__device__ __forceinline__ unsigned int dist_key(float m) {
    return 0x7F7FFFFFu - __float_as_uint(fmaxf(m, 0.0f));
}
__device__ __forceinline__ void bsplit(float v, unsigned short& hb, unsigned short& lb) {
    __nv_bfloat16 h = __float2bfloat16_rn(v);
    hb = __bfloat16_as_ushort(h);
    lb = __bfloat16_as_ushort(__float2bfloat16_rn(v - __bfloat162float(h)));
}
__device__ __forceinline__ unsigned int pk16(unsigned short lo, unsigned short hi) {
    return (unsigned int)lo | ((unsigned int)hi << 16);
}
__device__ __forceinline__ unsigned int smaddr(const void* p) {
    return (unsigned int)__cvta_generic_to_shared(p);
}

__device__ __forceinline__ void encodeA(unsigned short* row, float px, float py, float pz) {
    unsigned short qhx, qlx, qhy, qly, qhz, qlz, nh, nl;
    bsplit(-2.0f * px, qhx, qlx);
    bsplit(-2.0f * py, qhy, qly);
    bsplit(-2.0f * pz, qhz, qlz);
    bsplit(fmaf(px, px, fmaf(py, py, pz * pz)), nh, nl);
    const unsigned short one = 0x3F80;
    *(uint4*)(row)     = make_uint4(pk16(qhx, qhy), pk16(qhz, qlx), pk16(qly, qlz), pk16(qhx, qhy));
    *(uint4*)(row + 8) = make_uint4(pk16(qhz, qlx), pk16(qly, qlz), pk16(nh, nl), pk16(one, one));
}
__device__ __forceinline__ void encodeB(unsigned short* row, float gx, float gy, float gz) {
    unsigned short ghx, glx, ghy, gly, ghz, glz, wh, wl;
    bsplit(gx, ghx, glx);
    bsplit(gy, ghy, gly);
    bsplit(gz, ghz, glz);
    bsplit(fmaf(gx, gx, fmaf(gy, gy, gz * gz)), wh, wl);
    const unsigned short one = 0x3F80;
    *(uint4*)(row)     = make_uint4(pk16(ghx, ghy), pk16(ghz, ghx), pk16(ghy, ghz), pk16(glx, gly));
    *(uint4*)(row + 8) = make_uint4(pk16(glz, glx), pk16(gly, glz), pk16(one, one), pk16(wh, wl));
}

__global__ void __launch_bounds__(TPB, 7) chamfer_mma_kernel(
    const float* __restrict__ recon,
    const float* __restrict__ gt,
    float* __restrict__ out)
{
    __shared__ __align__(16) unsigned short sA[ROWS_PER_CTA * ROW_STRIDE];      // 6 KB
    __shared__ __align__(16) unsigned short sB[2][STAGE_COLS * ROW_STRIDE];     // 24 KB

    const int chunk  = blockIdx.x;          // row chunk (0..31)
    const int b      = blockIdx.y >> 2;     // batch
    const int csplit = blockIdx.y & 3;      // column quarter
    const int dir    = blockIdx.z;          // 0: recon rows; 1: gt rows
    const int tid    = threadIdx.x;
    const int lane   = tid & 31;
    const int wid    = tid >> 5;

    const float* src = dir ? gt : recon;    // rows (A)
    const float* dst = dir ? recon : gt;    // cols (B)
    const size_t colbase = (size_t)b * NPTS + csplit * COLS_PER_CTA;

    // --- encode A (128 rows, 1/thread) ---
    {
        const float* sp = src + ((size_t)b * NPTS + chunk * ROWS_PER_CTA + tid) * 3;
        encodeA(&sA[tid * ROW_STRIDE], sp[0], sp[1], sp[2]);
    }
    // --- encode B stage 0 into buffer 0 (2 cols/thread) ---
    {
        const float2* gp = (const float2*)(dst + colbase * 3 + 6 * tid);
        float2 f0 = gp[0], f1 = gp[1], f2 = gp[2];
        encodeB(&sB[0][(2 * tid)     * ROW_STRIDE], f0.x, f0.y, f1.x);
        encodeB(&sB[0][(2 * tid + 1) * ROW_STRIDE], f1.y, f2.x, f2.y);
    }
    __syncthreads();

    // --- load 2 A fragments per warp (rows wid*32 .. wid*32+31) ---
    unsigned int a0[4], a1[4];
    {
        unsigned int base = smaddr(sA) + ((lane & 15) * ROW_STRIDE * 2) + ((lane >> 4) << 4);
        unsigned int ad0 = base + (wid * 32) * (ROW_STRIDE * 2);
        unsigned int ad1 = base + (wid * 32 + 16) * (ROW_STRIDE * 2);
        asm volatile("ldmatrix.sync.aligned.m8n8.x4.shared.b16 {%0,%1,%2,%3}, [%4];"
                     : "=r"(a0[0]), "=r"(a0[1]), "=r"(a0[2]), "=r"(a0[3]) : "r"(ad0));
        asm volatile("ldmatrix.sync.aligned.m8n8.x4.shared.b16 {%0,%1,%2,%3}, [%4];"
                     : "=r"(a1[0]), "=r"(a1[1]), "=r"(a1[2]), "=r"(a1[3]) : "r"(ad1));
    }

    float rm0 = FLT_MAX, rm1 = FLT_MAX, rm2 = FLT_MAX, rm3 = FLT_MAX;
    const unsigned int bLaneOff = ((lane & 7) + ((lane >> 4) << 3)) * (ROW_STRIDE * 2)
                                + ((lane & 8) ? 16 : 0);
    const float fz = 0.0f;

#define DO_MMA(AF, BB0, BB1, RA, RB)                                            \
    {                                                                           \
        float d0, d1, d2, d3;                                                   \
        asm volatile(                                                           \
            "mma.sync.aligned.m16n8k16.row.col.f32.bf16.bf16.f32 "              \
            "{%0,%1,%2,%3}, {%4,%5,%6,%7}, {%8,%9}, {%10,%11,%12,%13};"         \
            : "=f"(d0), "=f"(d1), "=f"(d2), "=f"(d3)                            \
            : "r"(AF[0]), "r"(AF[1]), "r"(AF[2]), "r"(AF[3]),                   \
              "r"(BB0), "r"(BB1), "f"(fz), "f"(fz), "f"(fz), "f"(fz));          \
        RA = fminf(RA, fminf(d0, d1));                                          \
        RB = fminf(RB, fminf(d2, d3));                                          \
    }

    for (int s = 0; s < NSTAGES; ++s) {
        // Encode next stage into the idle buffer (overlaps with MMA below).
        if (s + 1 < NSTAGES) {
            const float2* gp = (const float2*)(dst
                + (colbase + (size_t)(s + 1) * STAGE_COLS) * 3 + 6 * tid);
            float2 f0 = gp[0], f1 = gp[1], f2 = gp[2];
            unsigned short* buf = sB[(s + 1) & 1];
            encodeB(&buf[(2 * tid)     * ROW_STRIDE], f0.x, f0.y, f1.x);
            encodeB(&buf[(2 * tid + 1) * ROW_STRIDE], f1.y, f2.x, f2.y);
        }

        unsigned int baddr = smaddr(sB[s & 1]) + bLaneOff;
        #pragma unroll
        for (int t = 0; t < UNITS_PER_STAGE; ++t) {
            unsigned int b0, b1, b2, b3;
            asm volatile("ldmatrix.sync.aligned.m8n8.x4.shared.b16 {%0,%1,%2,%3}, [%4];"
                         : "=r"(b0), "=r"(b1), "=r"(b2), "=r"(b3) : "r"(baddr));
            baddr += 16 * (ROW_STRIDE * 2);

            DO_MMA(a0, b0, b1, rm0, rm1);
            DO_MMA(a0, b2, b3, rm0, rm1);
            DO_MMA(a1, b0, b1, rm2, rm3);
            DO_MMA(a1, b2, b3, rm2, rm3);
        }
        __syncthreads();   // stage consumed + next stage encoded
    }
#undef DO_MMA

    // --- row-min combine across the 4 lanes sharing a row ---
    rm0 = fminf(rm0, __shfl_xor_sync(0xffffffffu, rm0, 1));
    rm0 = fminf(rm0, __shfl_xor_sync(0xffffffffu, rm0, 2));
    rm1 = fminf(rm1, __shfl_xor_sync(0xffffffffu, rm1, 1));
    rm1 = fminf(rm1, __shfl_xor_sync(0xffffffffu, rm1, 2));
    rm2 = fminf(rm2, __shfl_xor_sync(0xffffffffu, rm2, 1));
    rm2 = fminf(rm2, __shfl_xor_sync(0xffffffffu, rm2, 2));
    rm3 = fminf(rm3, __shfl_xor_sync(0xffffffffu, rm3, 1));
    rm3 = fminf(rm3, __shfl_xor_sync(0xffffffffu, rm3, 2));
    if ((lane & 3) == 0) {
        const int row   = chunk * ROWS_PER_CTA + wid * 32 + (lane >> 2);
        const int sbase = dir * BATCH * NPTS + b * NPTS;
        atomicMax(&g_maxkey[sbase + row],      dist_key(rm0));
        atomicMax(&g_maxkey[sbase + row + 8],  dist_key(rm1));
        atomicMax(&g_maxkey[sbase + row + 16], dist_key(rm2));
        atomicMax(&g_maxkey[sbase + row + 24], dist_key(rm3));
    }

    // --- elect last CTA to finalize ---
    __shared__ unsigned int s_last;
    __threadfence();
    __syncthreads();
    if (tid == 0) {
        unsigned int old = atomicAdd(&g_count, 1u);
        s_last = (old == NCTAS - 1) ? 1u : 0u;
    }
    __syncthreads();

    if (s_last) {
        __threadfence();   // all atomics visible
        float acc = 0.0f;
        const uint4* mv = (const uint4*)g_maxkey;
        #pragma unroll 4
        for (int s = tid; s < NSLOTS / 4; s += TPB) {
            uint4 v = mv[s];
            acc += __uint_as_float(0x7F7FFFFFu - v.x)
                 + __uint_as_float(0x7F7FFFFFu - v.y)
                 + __uint_as_float(0x7F7FFFFFu - v.z)
                 + __uint_as_float(0x7F7FFFFFu - v.w);
        }
        __shared__ float sred[TPB];
        sred[tid] = acc;
        __syncthreads();

        // Reset slots to identity for the next graph replay.
        uint4* mw = (uint4*)g_maxkey;
        const uint4 z4 = make_uint4(0u, 0u, 0u, 0u);
        #pragma unroll 4
        for (int s = tid; s < NSLOTS / 4; s += TPB) mw[s] = z4;

        #pragma unroll
        for (int s = TPB / 2; s > 0; s >>= 1) {
            if (tid < s) sred[tid] += sred[tid + s];
            __syncthreads();
        }
        if (tid == 0) {
            out[0] = sred[0] / (float)NSLOTS;   // == (mean1 + mean2) / 2
            g_count = 0;                        // reset for next replay
        }
    }
}

extern "C" void kernel_launch(void* const* d_in, const int* in_sizes, int n_in,
                              void* d_out, int out_size)
{
    const float* recon = (const float*)d_in[0];
    const float* gt    = (const float*)d_in[1];
    float* out = (float*)d_out;

    dim3 grid(ROWCHUNKS, COLSPLIT * BATCH, 2);   // 32 x 16 x 2 = 1024 CTAs
    chamfer_mma_kernel<<<grid, TPB>>>(recon, gt, out);
}

// round 17
// speedup vs baseline: 1.1020x; 1.1020x over previous
#include <cuda_runtime.h>
#include <cuda_bf16.h>
#include <float.h>

// Chamfer distance, B=4, N=M=4096, D=3 — tensor-core mma.sync, v6.
// = R13 mainloop with (a) STAGE_COLS=128 -> 18KB smem -> 7 CTAs/SM (regs<=73
// via launch_bounds) -> single 1024-CTA wave, no tail; (b) next stage's raw
// points prefetched into REGISTERS before the MMA loop and encoded after it,
// hiding the per-stage LDG latency behind tensor work.
// One m16n8k16 bf16 MMA yields 128 FINAL squared distances via exact 2-term
// bf16 split (k map:  A: qhi.xyz qlo.xyz qhi.xyz qlo.xyz np_hi np_lo 1 1
//                     B: ghi.xyz ghi.xyz glo.xyz glo.xyz 1 1 w_hi w_lo
//  dot = (qhi+qlo).(ghi+glo) + np + w = |p-g|^2, fp32 accum).
// 32 rows/warp (2 A frags), ldmatrix.x4 B frags (1 LDSM -> 4 HMMAs).
// Row mins in regs; both directions as role-swapped passes. Cross-CTA
// combine: atomicMax on key 0x7F7FFFFF - bits(d>=0) (zero-init identity,
// no init kernel); last CTA decodes/sums fixed-order, resets slots.

#define BATCH 4
#define NPTS  4096
#define TPB   128
#define ROWS_PER_CTA 128                     // 32 rows per warp
#define ROWCHUNKS (NPTS / ROWS_PER_CTA)      // 32
#define COLSPLIT 4
#define COLS_PER_CTA (NPTS / COLSPLIT)       // 1024
#define STAGE_COLS 128
#define NSTAGES (COLS_PER_CTA / STAGE_COLS)  // 8
#define UNITS_PER_STAGE (STAGE_COLS / 16)    // 8
#define ROW_STRIDE 24                        // bf16 elems per smem row (48B)
#define NSLOTS (2 * BATCH * NPTS)            // 32768
#define NCTAS (ROWCHUNKS * COLSPLIT * BATCH * 2)  // 1024

__device__ unsigned int g_maxkey[NSLOTS];    // 0 == key(FLT_MAX): identity
__device__ unsigned int g_count = 0;

__device__ __forceinline__ unsigned int dist_key(float m) {
    return 0x7F7FFFFFu - __float_as_uint(fmaxf(m, 0.0f));
}
__device__ __forceinline__ void bsplit(float v, unsigned short& hb, unsigned short& lb) {
    __nv_bfloat16 h = __float2bfloat16_rn(v);
    hb = __bfloat16_as_ushort(h);
    lb = __bfloat16_as_ushort(__float2bfloat16_rn(v - __bfloat162float(h)));
}
__device__ __forceinline__ unsigned int pk16(unsigned short lo, unsigned short hi) {
    return (unsigned int)lo | ((unsigned int)hi << 16);
}
__device__ __forceinline__ unsigned int smaddr(const void* p) {
    return (unsigned int)__cvta_generic_to_shared(p);
}

__device__ __forceinline__ void encodeA(unsigned short* row, float px, float py, float pz) {
    unsigned short qhx, qlx, qhy, qly, qhz, qlz, nh, nl;
    bsplit(-2.0f * px, qhx, qlx);
    bsplit(-2.0f * py, qhy, qly);
    bsplit(-2.0f * pz, qhz, qlz);
    bsplit(fmaf(px, px, fmaf(py, py, pz * pz)), nh, nl);
    const unsigned short one = 0x3F80;
    *(uint4*)(row)     = make_uint4(pk16(qhx, qhy), pk16(qhz, qlx), pk16(qly, qlz), pk16(qhx, qhy));
    *(uint4*)(row + 8) = make_uint4(pk16(qhz, qlx), pk16(qly, qlz), pk16(nh, nl), pk16(one, one));
}
__device__ __forceinline__ void encodeB(unsigned short* row, float gx, float gy, float gz) {
    unsigned short ghx, glx, ghy, gly, ghz, glz, wh, wl;
    bsplit(gx, ghx, glx);
    bsplit(gy, ghy, gly);
    bsplit(gz, ghz, glz);
    bsplit(fmaf(gx, gx, fmaf(gy, gy, gz * gz)), wh, wl);
    const unsigned short one = 0x3F80;
    *(uint4*)(row)     = make_uint4(pk16(ghx, ghy), pk16(ghz, ghx), pk16(ghy, ghz), pk16(glx, gly));
    *(uint4*)(row + 8) = make_uint4(pk16(glz, glx), pk16(gly, glz), pk16(one, one), pk16(wh, wl));
}

__global__ void __launch_bounds__(TPB, 7) chamfer_mma_kernel(
    const float* __restrict__ recon,
    const float* __restrict__ gt,
    float* __restrict__ out)
{
    __shared__ __align__(16) unsigned short sA[ROWS_PER_CTA * ROW_STRIDE];      // 6 KB
    __shared__ __align__(16) unsigned short sB[2][STAGE_COLS * ROW_STRIDE];     // 12 KB

    const int chunk  = blockIdx.x;          // row chunk (0..31)
    const int b      = blockIdx.y >> 2;     // batch
    const int csplit = blockIdx.y & 3;      // column quarter
    const int dir    = blockIdx.z;          // 0: recon rows; 1: gt rows
    const int tid    = threadIdx.x;
    const int lane   = tid & 31;
    const int wid    = tid >> 5;

    const float* src = dir ? gt : recon;    // rows (A)
    const float* dst = dir ? recon : gt;    // cols (B)
    // Each thread owns column (stage base + tid); 12B per point, coalesced.
    const float* colp = dst + ((size_t)b * NPTS + csplit * COLS_PER_CTA + tid) * 3;

    // --- encode A (128 rows, 1/thread) ---
    {
        const float* sp = src + ((size_t)b * NPTS + chunk * ROWS_PER_CTA + tid) * 3;
        encodeA(&sA[tid * ROW_STRIDE], sp[0], sp[1], sp[2]);
    }
    // --- encode B stage 0 into buffer 0 (1 col/thread) ---
    {
        float gx = colp[0], gy = colp[1], gz = colp[2];
        encodeB(&sB[0][tid * ROW_STRIDE], gx, gy, gz);
    }
    __syncthreads();

    // --- load 2 A fragments per warp (rows wid*32 .. wid*32+31) ---
    unsigned int a0[4], a1[4];
    {
        unsigned int base = smaddr(sA) + ((lane & 15) * ROW_STRIDE * 2) + ((lane >> 4) << 4);
        unsigned int ad0 = base + (wid * 32) * (ROW_STRIDE * 2);
        unsigned int ad1 = base + (wid * 32 + 16) * (ROW_STRIDE * 2);
        asm volatile("ldmatrix.sync.aligned.m8n8.x4.shared.b16 {%0,%1,%2,%3}, [%4];"
                     : "=r"(a0[0]), "=r"(a0[1]), "=r"(a0[2]), "=r"(a0[3]) : "r"(ad0));
        asm volatile("ldmatrix.sync.aligned.m8n8.x4.shared.b16 {%0,%1,%2,%3}, [%4];"
                     : "=r"(a1[0]), "=r"(a1[1]), "=r"(a1[2]), "=r"(a1[3]) : "r"(ad1));
    }

    float rm0 = FLT_MAX, rm1 = FLT_MAX, rm2 = FLT_MAX, rm3 = FLT_MAX;
    const unsigned int bLaneOff = ((lane & 7) + ((lane >> 4) << 3)) * (ROW_STRIDE * 2)
                                + ((lane & 8) ? 16 : 0);
    const float fz = 0.0f;

#define DO_MMA(AF, BB0, BB1, RA, RB)                                            \
    {                                                                           \
        float d0, d1, d2, d3;                                                   \
        asm volatile(                                                           \
            "mma.sync.aligned.m16n8k16.row.col.f32.bf16.bf16.f32 "              \
            "{%0,%1,%2,%3}, {%4,%5,%6,%7}, {%8,%9}, {%10,%11,%12,%13};"         \
            : "=f"(d0), "=f"(d1), "=f"(d2), "=f"(d3)                            \
            : "r"(AF[0]), "r"(AF[1]), "r"(AF[2]), "r"(AF[3]),                   \
              "r"(BB0), "r"(BB1), "f"(fz), "f"(fz), "f"(fz), "f"(fz));          \
        RA = fminf(RA, fminf(d0, d1));                                          \
        RB = fminf(RB, fminf(d2, d3));                                          \
    }

    for (int s = 0; s < NSTAGES; ++s) {
        // PREFETCH next stage's raw point into registers (LDG issues here,
        // completes during the MMA loop below — latency hidden).
        float nx = 0.0f, ny = 0.0f, nz = 0.0f;
        if (s + 1 < NSTAGES) {
            const float* np_ = colp + (size_t)(s + 1) * STAGE_COLS * 3;
            nx = np_[0]; ny = np_[1]; nz = np_[2];
        }

        unsigned int baddr = smaddr(sB[s & 1]) + bLaneOff;
        #pragma unroll
        for (int t = 0; t < UNITS_PER_STAGE; ++t) {
            unsigned int b0, b1, b2, b3;
            asm volatile("ldmatrix.sync.aligned.m8n8.x4.shared.b16 {%0,%1,%2,%3}, [%4];"
                         : "=r"(b0), "=r"(b1), "=r"(b2), "=r"(b3) : "r"(baddr));
            baddr += 16 * (ROW_STRIDE * 2);

            DO_MMA(a0, b0, b1, rm0, rm1);
            DO_MMA(a0, b2, b3, rm0, rm1);
            DO_MMA(a1, b0, b1, rm2, rm3);
            DO_MMA(a1, b2, b3, rm2, rm3);
        }

        // Encode the prefetched point into the idle buffer (consumed next
        // stage; buffer was last read in stage s-1, barrier below orders it).
        if (s + 1 < NSTAGES)
            encodeB(&sB[(s + 1) & 1][tid * ROW_STRIDE], nx, ny, nz);
        __syncthreads();   // stage consumed + next stage encoded
    }
#undef DO_MMA

    // --- row-min combine across the 4 lanes sharing a row ---
    rm0 = fminf(rm0, __shfl_xor_sync(0xffffffffu, rm0, 1));
    rm0 = fminf(rm0, __shfl_xor_sync(0xffffffffu, rm0, 2));
    rm1 = fminf(rm1, __shfl_xor_sync(0xffffffffu, rm1, 1));
    rm1 = fminf(rm1, __shfl_xor_sync(0xffffffffu, rm1, 2));
    rm2 = fminf(rm2, __shfl_xor_sync(0xffffffffu, rm2, 1));
    rm2 = fminf(rm2, __shfl_xor_sync(0xffffffffu, rm2, 2));
    rm3 = fminf(rm3, __shfl_xor_sync(0xffffffffu, rm3, 1));
    rm3 = fminf(rm3, __shfl_xor_sync(0xffffffffu, rm3, 2));
    if ((lane & 3) == 0) {
        const int row   = chunk * ROWS_PER_CTA + wid * 32 + (lane >> 2);
        const int sbase = dir * BATCH * NPTS + b * NPTS;
        atomicMax(&g_maxkey[sbase + row],      dist_key(rm0));
        atomicMax(&g_maxkey[sbase + row + 8],  dist_key(rm1));
        atomicMax(&g_maxkey[sbase + row + 16], dist_key(rm2));
        atomicMax(&g_maxkey[sbase + row + 24], dist_key(rm3));
    }

    // --- elect last CTA to finalize ---
    __shared__ unsigned int s_last;
    __threadfence();
    __syncthreads();
    if (tid == 0) {
        unsigned int old = atomicAdd(&g_count, 1u);
        s_last = (old == NCTAS - 1) ? 1u : 0u;
    }
    __syncthreads();

    if (s_last) {
        __threadfence();   // all atomics visible
        float acc = 0.0f;
        const uint4* mv = (const uint4*)g_maxkey;
        #pragma unroll 4
        for (int s = tid; s < NSLOTS / 4; s += TPB) {
            uint4 v = mv[s];
            acc += __uint_as_float(0x7F7FFFFFu - v.x)
                 + __uint_as_float(0x7F7FFFFFu - v.y)
                 + __uint_as_float(0x7F7FFFFFu - v.z)
                 + __uint_as_float(0x7F7FFFFFu - v.w);
        }
        __shared__ float sred[TPB];
        sred[tid] = acc;
        __syncthreads();

        // Reset slots to identity for the next graph replay.
        uint4* mw = (uint4*)g_maxkey;
        const uint4 z4 = make_uint4(0u, 0u, 0u, 0u);
        #pragma unroll 4
        for (int s = tid; s < NSLOTS / 4; s += TPB) mw[s] = z4;

        #pragma unroll
        for (int s = TPB / 2; s > 0; s >>= 1) {
            if (tid < s) sred[tid] += sred[tid + s];
            __syncthreads();
        }
        if (tid == 0) {
            out[0] = sred[0] / (float)NSLOTS;   // == (mean1 + mean2) / 2
            g_count = 0;                        // reset for next replay
        }
    }
}

extern "C" void kernel_launch(void* const* d_in, const int* in_sizes, int n_in,
                              void* d_out, int out_size)
{
    const float* recon = (const float*)d_in[0];
    const float* gt    = (const float*)d_in[1];
    float* out = (float*)d_out;

    dim3 grid(ROWCHUNKS, COLSPLIT * BATCH, 2);   // 32 x 16 x 2 = 1024 CTAs
    chamfer_mma_kernel<<<grid, TPB>>>(recon, gt, out);
}